// round 1
// baseline (speedup 1.0000x reference)
#include <cuda_runtime.h>
#include <math.h>

// Problem constants
#define FF 3
#define NN 20000
#define DD 256
#define OO 256
#define EE 320000

// ---------------- scratch (__device__ globals; no allocation allowed) -------
__device__ float g_xg  [FF * NN * OO];   // x @ Wg
__device__ float g_gcn [FF * NN * OO];   // gcn accumulator (init = self-loop term)
__device__ float g_res [FF * NN * OO];   // x @ Wr^T
__device__ float g_gate[FF * NN * OO];   // sigmoid(x @ Wh)
__device__ float g_deg [NN];
__device__ float g_dinv[NN];
__device__ float g_coef[EE];

// ---------------- K1: init degree with improved self-loop weight 2.0 --------
__global__ void init_deg_kernel() {
    int n = blockIdx.x * blockDim.x + threadIdx.x;
    if (n < NN) g_deg[n] = 2.0f;
}

// ---------------- K2: accumulate edge weights into deg[col] -----------------
__global__ void deg_acc_kernel(const int* __restrict__ ei,
                               const float* __restrict__ w) {
    int e = blockIdx.x * blockDim.x + threadIdx.x;
    if (e < EE) {
        int c = ei[EE + e];
        atomicAdd(&g_deg[c], w[e]);
    }
}

// ---------------- K3: dinv = rsqrt(deg) -------------------------------------
__global__ void dinv_kernel() {
    int n = blockIdx.x * blockDim.x + threadIdx.x;
    if (n < NN) {
        float d = g_deg[n];
        g_dinv[n] = (d > 0.0f) ? rsqrtf(d) : 0.0f;
    }
}

// ---------------- K4: per-edge normalization coefficient --------------------
__global__ void coef_kernel(const int* __restrict__ ei,
                            const float* __restrict__ w) {
    int e = blockIdx.x * blockDim.x + threadIdx.x;
    if (e < EE) {
        int r = ei[e];
        int c = ei[EE + e];
        g_coef[e] = g_dinv[r] * w[e] * g_dinv[c];
    }
}

// ---------------- K5: fused triple GEMM + epilogue ---------------------------
// Computes, per field f:
//   xg   = x @ Wg                      (Wg: [D,O], row-major O contiguous)
//   res  = x @ Wr^T                    (Wr: [O,D], row-major D contiguous)
//   gate = sigmoid(x @ Wh)             (Wh: [D,O])
// Epilogue also seeds gcn with the self-loop term 2*dinv^2 * xg.
// Tiling: BM=64, BN=64, BK=16; 256 threads; 4x4 micro-tile per thread.
#define BM 64
#define BN 64
#define BK 16
#define SPAD 68   // smem row stride in floats: 68*4 = 272 bytes (16B aligned)

__global__ __launch_bounds__(256)
void fused_gemm_kernel(const float* __restrict__ x,
                       const float* __restrict__ Wg,
                       const float* __restrict__ Wr,
                       const float* __restrict__ Wh) {
    __shared__ float As[BK][SPAD];
    __shared__ float Bg[BK][SPAD];
    __shared__ float Br[BK][SPAD];
    __shared__ float Bh[BK][SPAD];

    const int f     = blockIdx.z;
    const int mBase = blockIdx.x * BM;
    const int nBase = blockIdx.y * BN;

    const float* xf = x  + (size_t)f * NN * DD;
    const float* wg = Wg + (size_t)f * DD * OO;
    const float* wr = Wr + (size_t)f * OO * DD;
    const float* wh = Wh + (size_t)f * DD * OO;

    const int tid = threadIdx.x;
    const int tx  = tid & 15;   // 0..15 -> n
    const int ty  = tid >> 4;   // 0..15 -> m

    // load-index decompositions
    const int ar  = tid >> 2;          // A row within tile (0..63)
    const int ac4 = (tid & 3) * 4;     // A col group (0,4,8,12)
    const int br  = tid >> 4;          // B(k-major) row (0..15)
    const int bc4 = (tid & 15) * 4;    // B col group
    const int rn  = tid >> 2;          // Wr out-row within tile (0..63)
    const int rk4 = (tid & 3) * 4;     // Wr k group

    float acc_g[4][4] = {};
    float acc_r[4][4] = {};
    float acc_h[4][4] = {};

    const int gm = mBase + ar;
    const bool m_ok = (gm < NN);

    for (int kb = 0; kb < DD; kb += BK) {
        // ---- A tile: x[mBase:mBase+64, kb:kb+16], stored transposed As[k][m]
        float4 av = make_float4(0.f, 0.f, 0.f, 0.f);
        if (m_ok) av = *(const float4*)(xf + (size_t)gm * DD + kb + ac4);
        As[ac4 + 0][ar] = av.x;
        As[ac4 + 1][ar] = av.y;
        As[ac4 + 2][ar] = av.z;
        As[ac4 + 3][ar] = av.w;

        // ---- Bg / Bh tiles: W[kb:kb+16, nBase:nBase+64] (natural layout)
        {
            float4 v = *(const float4*)(wg + (size_t)(kb + br) * OO + nBase + bc4);
            *(float4*)&Bg[br][bc4] = v;
        }
        {
            float4 v = *(const float4*)(wh + (size_t)(kb + br) * OO + nBase + bc4);
            *(float4*)&Bh[br][bc4] = v;
        }

        // ---- Br tile: Wr[nBase+rn, kb:kb+16] transposed into Br[k][n]
        {
            float4 v = *(const float4*)(wr + (size_t)(nBase + rn) * DD + kb + rk4);
            Br[rk4 + 0][rn] = v.x;
            Br[rk4 + 1][rn] = v.y;
            Br[rk4 + 2][rn] = v.z;
            Br[rk4 + 3][rn] = v.w;
        }

        __syncthreads();

        #pragma unroll
        for (int k = 0; k < BK; k++) {
            float4 a  = *(const float4*)&As[k][ty * 4];
            float4 bg = *(const float4*)&Bg[k][tx * 4];
            float4 bb = *(const float4*)&Br[k][tx * 4];
            float4 bh = *(const float4*)&Bh[k][tx * 4];
            const float am[4] = {a.x, a.y, a.z, a.w};
            const float vg[4] = {bg.x, bg.y, bg.z, bg.w};
            const float vr[4] = {bb.x, bb.y, bb.z, bb.w};
            const float vh[4] = {bh.x, bh.y, bh.z, bh.w};
            #pragma unroll
            for (int i = 0; i < 4; i++) {
                #pragma unroll
                for (int j = 0; j < 4; j++) {
                    acc_g[i][j] = fmaf(am[i], vg[j], acc_g[i][j]);
                    acc_r[i][j] = fmaf(am[i], vr[j], acc_r[i][j]);
                    acc_h[i][j] = fmaf(am[i], vh[j], acc_h[i][j]);
                }
            }
        }

        __syncthreads();
    }

    // ---- epilogue: write xg, gcn(self-loop seed), res, gate -----------------
    #pragma unroll
    for (int i = 0; i < 4; i++) {
        int m = mBase + ty * 4 + i;
        if (m >= NN) continue;
        float di = g_dinv[m];
        float sl = 2.0f * di * di;
        size_t base = ((size_t)f * NN + m) * OO + nBase + tx * 4;

        float4 xv, gv, rv, hv;
        xv.x = acc_g[i][0]; xv.y = acc_g[i][1]; xv.z = acc_g[i][2]; xv.w = acc_g[i][3];
        gv.x = sl * xv.x;   gv.y = sl * xv.y;   gv.z = sl * xv.z;   gv.w = sl * xv.w;
        rv.x = acc_r[i][0]; rv.y = acc_r[i][1]; rv.z = acc_r[i][2]; rv.w = acc_r[i][3];
        hv.x = 1.0f / (1.0f + expf(-acc_h[i][0]));
        hv.y = 1.0f / (1.0f + expf(-acc_h[i][1]));
        hv.z = 1.0f / (1.0f + expf(-acc_h[i][2]));
        hv.w = 1.0f / (1.0f + expf(-acc_h[i][3]));

        *(float4*)&g_xg  [base] = xv;
        *(float4*)&g_gcn [base] = gv;
        *(float4*)&g_res [base] = rv;
        *(float4*)&g_gate[base] = hv;
    }
}

// ---------------- K6: edge scatter with atomics ------------------------------
// One thread handles one (edge, float4-of-O); blockIdx.y = field.
// 64 threads share an edge -> row/col/coef loads broadcast from L1.
__global__ __launch_bounds__(256)
void scatter_kernel(const int* __restrict__ ei) {
    int idx = blockIdx.x * blockDim.x + threadIdx.x;   // over EE * 64
    int f   = blockIdx.y;
    int e   = idx >> 6;       // edge
    int j   = idx & 63;       // float4 slot within O=256
    if (e >= EE) return;

    int   r    = ei[e];
    int   c    = ei[EE + e];
    float coef = g_coef[e];

    const float4* src = (const float4*)(g_xg + ((size_t)f * NN + r) * OO);
    float*        dst = g_gcn + ((size_t)f * NN + c) * OO;

    float4 v = src[j];
    int o = j * 4;
    atomicAdd(dst + o + 0, coef * v.x);
    atomicAdd(dst + o + 1, coef * v.y);
    atomicAdd(dst + o + 2, coef * v.z);
    atomicAdd(dst + o + 3, coef * v.w);
}

// ---------------- K7: highway combine + leaky_relu ---------------------------
__global__ __launch_bounds__(256)
void combine_kernel(float* __restrict__ out) {
    int i = blockIdx.x * blockDim.x + threadIdx.x;     // float4 index
    const int total4 = FF * NN * OO / 4;
    if (i >= total4) return;

    float4 g = ((const float4*)g_gate)[i];
    float4 a = ((const float4*)g_gcn)[i];
    float4 r = ((const float4*)g_res)[i];

    float4 y;
    y.x = g.x * a.x + (1.0f - g.x) * r.x;
    y.y = g.y * a.y + (1.0f - g.y) * r.y;
    y.z = g.z * a.z + (1.0f - g.z) * r.z;
    y.w = g.w * a.w + (1.0f - g.w) * r.w;

    y.x = (y.x >= 0.0f) ? y.x : 0.01f * y.x;
    y.y = (y.y >= 0.0f) ? y.y : 0.01f * y.y;
    y.z = (y.z >= 0.0f) ? y.z : 0.01f * y.z;
    y.w = (y.w >= 0.0f) ? y.w : 0.01f * y.w;

    ((float4*)out)[i] = y;
}

// ---------------- launch ------------------------------------------------------
extern "C" void kernel_launch(void* const* d_in, const int* in_sizes, int n_in,
                              void* d_out, int out_size) {
    const float* x  = (const float*)d_in[0];
    const int*   ei = (const int*)  d_in[1];
    const float* w  = (const float*)d_in[2];
    const float* Wg = (const float*)d_in[3];
    const float* Wr = (const float*)d_in[4];
    const float* Wh = (const float*)d_in[5];
    float* out = (float*)d_out;

    init_deg_kernel<<<(NN + 255) / 256, 256>>>();
    deg_acc_kernel <<<(EE + 255) / 256, 256>>>(ei, w);
    dinv_kernel    <<<(NN + 255) / 256, 256>>>();
    coef_kernel    <<<(EE + 255) / 256, 256>>>(ei, w);

    dim3 ggrid((NN + BM - 1) / BM, OO / BN, FF);     // (313, 4, 3)
    fused_gemm_kernel<<<ggrid, 256>>>(x, Wg, Wr, Wh);

    dim3 sgrid((EE * 64 + 255) / 256, FF);           // (80000, 3)
    scatter_kernel<<<sgrid, 256>>>(ei);

    int total4 = FF * NN * OO / 4;
    combine_kernel<<<(total4 + 255) / 256, 256>>>(out);
}

// round 3
// speedup vs baseline: 2.4464x; 2.4464x over previous
#include <cuda_runtime.h>
#include <math.h>
#include <stdint.h>

// Problem constants
#define FF 3
#define NN 20000
#define NP 20096          // NN padded to multiple of 128 (M-tile)
#define DD 256
#define OO 256
#define NC 768            // combined N: [xg | res | gate]
#define EE 320000
#define NEG_SLOPE 0.01f

// ---------------- scratch (__device__ globals; no allocation allowed) -------
__device__ float g_xa  [FF * NP * DD];   // x rounded to tf32, padded rows
__device__ float g_bc  [FF * DD * NC];   // combined B (tf32): Wg | Wr^T | Wh
__device__ float g_xg  [FF * NN * OO];   // x @ Wg
__device__ float g_gcn [FF * NN * OO];   // gcn accumulator (seeded with self-loop)
__device__ float g_res [FF * NN * OO];   // x @ Wr^T
__device__ float g_gate[FF * NN * OO];   // sigmoid(x @ Wh)
__device__ float g_deg [NN];
__device__ float g_dinv[NN];
__device__ float g_coef[EE];

// ---------------- helpers -----------------------------------------------------
__device__ __forceinline__ float f2tf32(float f) {
    uint32_t r;
    asm("cvt.rna.tf32.f32 %0, %1;" : "=r"(r) : "f"(f));
    return __uint_as_float(r);
}
__device__ __forceinline__ uint32_t smem_u32(const void* p) {
    uint32_t a;
    asm("{ .reg .u64 t; cvta.to.shared.u64 t, %1; cvt.u32.u64 %0, t; }"
        : "=r"(a) : "l"(p));
    return a;
}
__device__ __forceinline__ void cp_async16(uint32_t dst, const void* src) {
    asm volatile("cp.async.cg.shared.global [%0], [%1], 16;"
                 :: "r"(dst), "l"(src) : "memory");
}
__device__ __forceinline__ void cp_commit() {
    asm volatile("cp.async.commit_group;" ::: "memory");
}
template <int N>
__device__ __forceinline__ void cp_wait() {
    asm volatile("cp.async.wait_group %0;" :: "n"(N) : "memory");
}
__device__ __forceinline__ void mma_tf32(float* c, const uint32_t* a, const uint32_t* b) {
    asm volatile(
        "mma.sync.aligned.m16n8k8.row.col.f32.tf32.tf32.f32 "
        "{%0,%1,%2,%3}, {%4,%5,%6,%7}, {%8,%9}, {%0,%1,%2,%3};"
        : "+f"(c[0]), "+f"(c[1]), "+f"(c[2]), "+f"(c[3])
        : "r"(a[0]), "r"(a[1]), "r"(a[2]), "r"(a[3]), "r"(b[0]), "r"(b[1]));
}

// ---------------- K1-K4: degree / normalization prep -------------------------
__global__ void init_deg_kernel() {
    int n = blockIdx.x * blockDim.x + threadIdx.x;
    if (n < NN) g_deg[n] = 2.0f;
}
__global__ void deg_acc_kernel(const int* __restrict__ ei, const float* __restrict__ w) {
    int e = blockIdx.x * blockDim.x + threadIdx.x;
    if (e < EE) atomicAdd(&g_deg[ei[EE + e]], w[e]);
}
__global__ void dinv_kernel() {
    int n = blockIdx.x * blockDim.x + threadIdx.x;
    if (n < NN) {
        float d = g_deg[n];
        g_dinv[n] = (d > 0.0f) ? rsqrtf(d) : 0.0f;
    }
}
__global__ void coef_kernel(const int* __restrict__ ei, const float* __restrict__ w) {
    int e = blockIdx.x * blockDim.x + threadIdx.x;
    if (e < EE) g_coef[e] = g_dinv[ei[e]] * w[e] * g_dinv[ei[EE + e]];
}

// ---------------- K5a: round x to tf32 into padded buffer --------------------
__global__ __launch_bounds__(256)
void cvt_x_kernel(const float* __restrict__ x) {
    int i = blockIdx.x * blockDim.x + threadIdx.x;   // float4 index within field
    int f = blockIdx.y;
    const int per_field4 = NN * DD / 4;              // 1,280,000
    if (i >= per_field4) return;
    float4 v = *(const float4*)(x + (size_t)f * NN * DD + (size_t)i * 4);
    v.x = f2tf32(v.x); v.y = f2tf32(v.y); v.z = f2tf32(v.z); v.w = f2tf32(v.w);
    *(float4*)(g_xa + (size_t)f * NP * DD + (size_t)i * 4) = v;
}

// ---------------- K5b: build combined B matrix (tf32) ------------------------
// g_bc[f][k][n]: n<256 -> Wg[f][k][n]; 256<=n<512 -> Wr[f][n-256][k]; else Wh.
__global__ __launch_bounds__(256)
void build_bc_kernel(const float* __restrict__ Wg, const float* __restrict__ Wr,
                     const float* __restrict__ Wh) {
    int i = blockIdx.x * blockDim.x + threadIdx.x;   // over DD*NC = 196608
    int f = blockIdx.y;
    if (i >= DD * NC) return;
    int k = i / NC;
    int n = i - k * NC;
    float v;
    if (n < 256)       v = Wg[(size_t)f * DD * OO + (size_t)k * OO + n];
    else if (n < 512)  v = Wr[(size_t)f * OO * DD + (size_t)(n - 256) * DD + k];
    else               v = Wh[(size_t)f * DD * OO + (size_t)k * OO + (n - 512)];
    g_bc[(size_t)f * DD * NC + i] = f2tf32(v);
}

// ---------------- K6: HMMA tf32 fused GEMM ------------------------------------
// C[f] = Xa[f] (NPx256) @ Bc[f] (256x768), CTA tile 128x128x32.
// 8 warps: 4 along M (32 rows), 2 along N (64 cols). mma m16n8k8 tf32.
#define BM 128
#define BN 128
#define BK 32
#define ASTRIDE 36      // floats; banks (4m+k)%32 distinct for frag loads
#define BSTRIDE 136     // floats; banks (8k+n)%32 distinct for frag loads
#define A_BYTES (BM * ASTRIDE * 4)   // 18432
#define B_BYTES (BK * BSTRIDE * 4)   // 17408
#define SMEM_GEMM (2 * (A_BYTES + B_BYTES))  // 71680

__global__ __launch_bounds__(256, 2)
void gemm_kernel() {
    extern __shared__ float sm[];
    const uint32_t smb = smem_u32(sm);
    // layout: A0 | A1 | B0 | B1
    const uint32_t smA[2] = { smb, smb + A_BYTES };
    const uint32_t smB[2] = { smb + 2 * A_BYTES, smb + 2 * A_BYTES + B_BYTES };

    const int tid = threadIdx.x;
    const int wid = tid >> 5;
    const int lid = tid & 31;
    const int gid = lid >> 2;       // 0..7
    const int tig = lid & 3;        // 0..3
    const int wm  = wid & 3;        // warp M index (0..3)
    const int wn  = wid >> 2;       // warp N index (0..1)

    const int f     = blockIdx.z;
    const int mBase = blockIdx.x * BM;
    const int nBase = blockIdx.y * BN;

    const float* aSrc = g_xa + (size_t)f * NP * DD;
    const float* bSrc = g_bc + (size_t)f * DD * NC;

    // per-thread cp.async coordinates
    const int ar = tid >> 1;                 // A row 0..127
    const int aq = (tid & 1) * 4;            // A float4 col {0,4}: covers 8 with stride
    const int br = tid >> 3;                 // B k-row 0..31
    const int bq = (tid & 7) * 4;            // B float4 col group

    // prefetch chunk 0
    {
        const float* ap = aSrc + (size_t)(mBase + ar) * DD + 0 + aq;
        cp_async16(smA[0] + (uint32_t)(ar * ASTRIDE + aq) * 4, ap);
        cp_async16(smA[0] + (uint32_t)(ar * ASTRIDE + aq + 8) * 4, ap + 8);
        cp_async16(smA[0] + (uint32_t)(ar * ASTRIDE + aq + 16) * 4, ap + 16);
        cp_async16(smA[0] + (uint32_t)(ar * ASTRIDE + aq + 24) * 4, ap + 24);
        const float* bp = bSrc + (size_t)br * NC + nBase + bq;
        cp_async16(smB[0] + (uint32_t)(br * BSTRIDE + bq) * 4, bp);
        cp_async16(smB[0] + (uint32_t)(br * BSTRIDE + bq + 32) * 4, bp + 32);
        cp_async16(smB[0] + (uint32_t)(br * BSTRIDE + bq + 64) * 4, bp + 64);
        cp_async16(smB[0] + (uint32_t)(br * BSTRIDE + bq + 96) * 4, bp + 96);
        cp_commit();
    }

    float c[2][8][4];
    #pragma unroll
    for (int im = 0; im < 2; im++)
        #pragma unroll
        for (int in = 0; in < 8; in++)
            #pragma unroll
            for (int r = 0; r < 4; r++) c[im][in][r] = 0.0f;

    for (int kc = 0; kc < 8; kc++) {
        const int buf = kc & 1;

        if (kc < 7) {
            const int nb = buf ^ 1;
            const int kcol = (kc + 1) * BK;
            const float* ap = aSrc + (size_t)(mBase + ar) * DD + kcol + aq;
            cp_async16(smA[nb] + (uint32_t)(ar * ASTRIDE + aq) * 4, ap);
            cp_async16(smA[nb] + (uint32_t)(ar * ASTRIDE + aq + 8) * 4, ap + 8);
            cp_async16(smA[nb] + (uint32_t)(ar * ASTRIDE + aq + 16) * 4, ap + 16);
            cp_async16(smA[nb] + (uint32_t)(ar * ASTRIDE + aq + 24) * 4, ap + 24);
            const float* bp = bSrc + (size_t)(kcol + br) * NC + nBase + bq;
            cp_async16(smB[nb] + (uint32_t)(br * BSTRIDE + bq) * 4, bp);
            cp_async16(smB[nb] + (uint32_t)(br * BSTRIDE + bq + 32) * 4, bp + 32);
            cp_async16(smB[nb] + (uint32_t)(br * BSTRIDE + bq + 64) * 4, bp + 64);
            cp_async16(smB[nb] + (uint32_t)(br * BSTRIDE + bq + 96) * 4, bp + 96);
            cp_commit();
            cp_wait<1>();
        } else {
            cp_wait<0>();
        }
        __syncthreads();

        const float* As = sm + (buf ? BM * ASTRIDE : 0);
        const float* Bs = sm + 2 * BM * ASTRIDE + (buf ? BK * BSTRIDE : 0);

        #pragma unroll
        for (int ks = 0; ks < 4; ks++) {
            const int k0 = ks * 8;
            uint32_t a[2][4];
            #pragma unroll
            for (int im = 0; im < 2; im++) {
                const int m0 = wm * 32 + im * 16 + gid;
                a[im][0] = __float_as_uint(As[(m0)     * ASTRIDE + k0 + tig]);
                a[im][1] = __float_as_uint(As[(m0 + 8) * ASTRIDE + k0 + tig]);
                a[im][2] = __float_as_uint(As[(m0)     * ASTRIDE + k0 + tig + 4]);
                a[im][3] = __float_as_uint(As[(m0 + 8) * ASTRIDE + k0 + tig + 4]);
            }
            uint32_t b[8][2];
            #pragma unroll
            for (int in = 0; in < 8; in++) {
                const int n0 = wn * 64 + in * 8 + gid;
                b[in][0] = __float_as_uint(Bs[(k0 + tig)     * BSTRIDE + n0]);
                b[in][1] = __float_as_uint(Bs[(k0 + tig + 4) * BSTRIDE + n0]);
            }
            #pragma unroll
            for (int im = 0; im < 2; im++)
                #pragma unroll
                for (int in = 0; in < 8; in++)
                    mma_tf32(c[im][in], a[im], b[in]);
        }
        __syncthreads();
    }

    // ---- epilogue: write to xg/gcn, res, gate ------------------------------
    const int nb0 = nBase + wn * 64;      // 64-aligned => single matrix per warp
    const int gsel = nb0 >> 8;            // 0: xg, 1: res, 2: gate
    const int o0 = nb0 & 255;

    #pragma unroll
    for (int im = 0; im < 2; im++) {
        const int r0 = mBase + wm * 32 + im * 16 + gid;
        #pragma unroll
        for (int half = 0; half < 2; half++) {
            const int m = r0 + half * 8;
            if (m >= NN) continue;
            size_t rowbase = ((size_t)f * NN + m) * OO;
            if (gsel == 0) {
                const float di = g_dinv[m];
                const float sl = 2.0f * di * di;
                #pragma unroll
                for (int in = 0; in < 8; in++) {
                    const int o = o0 + in * 8 + 2 * tig;
                    float2 v = make_float2(c[im][in][half * 2], c[im][in][half * 2 + 1]);
                    *(float2*)&g_xg[rowbase + o] = v;
                    *(float2*)&g_gcn[rowbase + o] = make_float2(sl * v.x, sl * v.y);
                }
            } else if (gsel == 1) {
                #pragma unroll
                for (int in = 0; in < 8; in++) {
                    const int o = o0 + in * 8 + 2 * tig;
                    *(float2*)&g_res[rowbase + o] =
                        make_float2(c[im][in][half * 2], c[im][in][half * 2 + 1]);
                }
            } else {
                #pragma unroll
                for (int in = 0; in < 8; in++) {
                    const int o = o0 + in * 8 + 2 * tig;
                    float2 v;
                    v.x = 1.0f / (1.0f + __expf(-c[im][in][half * 2]));
                    v.y = 1.0f / (1.0f + __expf(-c[im][in][half * 2 + 1]));
                    *(float2*)&g_gate[rowbase + o] = v;
                }
            }
        }
    }
}

// ---------------- K7: edge scatter with vector reductions --------------------
__global__ __launch_bounds__(256)
void scatter_kernel(const int* __restrict__ ei) {
    int idx = blockIdx.x * blockDim.x + threadIdx.x;   // over EE * 64
    int f   = blockIdx.y;
    int e   = idx >> 6;
    int j   = idx & 63;
    if (e >= EE) return;

    int   r    = ei[e];
    int   c    = ei[EE + e];
    float coef = g_coef[e];

    const float4* src = (const float4*)(g_xg + ((size_t)f * NN + r) * OO);
    float*        dst = g_gcn + ((size_t)f * NN + c) * OO + j * 4;

    float4 v = src[j];
    asm volatile("red.global.add.v4.f32 [%0], {%1, %2, %3, %4};"
                 :: "l"(dst), "f"(coef * v.x), "f"(coef * v.y),
                    "f"(coef * v.z), "f"(coef * v.w)
                 : "memory");
}

// ---------------- K8: highway combine + leaky_relu ---------------------------
__global__ __launch_bounds__(256)
void combine_kernel(float* __restrict__ out) {
    int i = blockIdx.x * blockDim.x + threadIdx.x;     // float4 index
    const int total4 = FF * NN * OO / 4;
    if (i >= total4) return;

    float4 g = ((const float4*)g_gate)[i];
    float4 a = ((const float4*)g_gcn)[i];
    float4 r = ((const float4*)g_res)[i];

    float4 y;
    y.x = g.x * a.x + (1.0f - g.x) * r.x;
    y.y = g.y * a.y + (1.0f - g.y) * r.y;
    y.z = g.z * a.z + (1.0f - g.z) * r.z;
    y.w = g.w * a.w + (1.0f - g.w) * r.w;

    y.x = (y.x >= 0.0f) ? y.x : NEG_SLOPE * y.x;
    y.y = (y.y >= 0.0f) ? y.y : NEG_SLOPE * y.y;
    y.z = (y.z >= 0.0f) ? y.z : NEG_SLOPE * y.z;
    y.w = (y.w >= 0.0f) ? y.w : NEG_SLOPE * y.w;

    ((float4*)out)[i] = y;
}

// ---------------- launch ------------------------------------------------------
extern "C" void kernel_launch(void* const* d_in, const int* in_sizes, int n_in,
                              void* d_out, int out_size) {
    const float* x  = (const float*)d_in[0];
    const int*   ei = (const int*)  d_in[1];
    const float* w  = (const float*)d_in[2];
    const float* Wg = (const float*)d_in[3];
    const float* Wr = (const float*)d_in[4];
    const float* Wh = (const float*)d_in[5];
    float* out = (float*)d_out;

    init_deg_kernel<<<(NN + 255) / 256, 256>>>();
    deg_acc_kernel <<<(EE + 255) / 256, 256>>>(ei, w);
    dinv_kernel    <<<(NN + 255) / 256, 256>>>();
    coef_kernel    <<<(EE + 255) / 256, 256>>>(ei, w);

    {
        int per_field4 = NN * DD / 4;
        dim3 grid((per_field4 + 255) / 256, FF);
        cvt_x_kernel<<<grid, 256>>>(x);
    }
    {
        dim3 grid((DD * NC + 255) / 256, FF);
        build_bc_kernel<<<grid, 256>>>(Wg, Wr, Wh);
    }

    cudaFuncSetAttribute(gemm_kernel,
                         cudaFuncAttributeMaxDynamicSharedMemorySize, SMEM_GEMM);
    dim3 ggrid(NP / BM, NC / BN, FF);    // (157, 6, 3)
    gemm_kernel<<<ggrid, 256, SMEM_GEMM>>>();

    dim3 sgrid((EE * 64 + 255) / 256, FF);   // (80000, 3)
    scatter_kernel<<<sgrid, 256>>>(ei);

    int total4 = FF * NN * OO / 4;
    combine_kernel<<<(total4 + 255) / 256, 256>>>(out);
}

// round 4
// speedup vs baseline: 3.3662x; 1.3760x over previous
#include <cuda_runtime.h>
#include <math.h>
#include <stdint.h>

// Problem constants
#define FF 3
#define NN 20000
#define NP 20096          // NN padded to multiple of 128 (M-tile)
#define DD 256
#define OO 256
#define NC 768            // combined N: [xg | res | gate]
#define EE 320000
#define NEG_SLOPE 0.01f

// ---------------- scratch (__device__ globals; no allocation allowed) -------
__device__ float g_xa  [FF * NP * DD];   // x rounded to tf32, padded rows
__device__ float g_bc  [FF * DD * NC];   // combined B (tf32): Wg | Wr^T | Wh
__device__ float g_xg  [FF * NN * OO];   // x @ Wg
__device__ float g_res [FF * NN * OO];   // x @ Wr^T
__device__ float g_gate[FF * NN * OO];   // sigmoid(x @ Wh)
__device__ float g_deg [NN];
__device__ float g_dinv[NN];
__device__ int   g_cnt [NN];             // in-degree (edges only)
__device__ int   g_off [NN];             // CSR offsets (stable)
__device__ int   g_off2[NN];             // CSR fill cursors
__device__ int   g_srow [EE];            // edge src rows, sorted by dst
__device__ float g_scoef[EE];            // edge coefs, sorted by dst

// ---------------- helpers -----------------------------------------------------
__device__ __forceinline__ float f2tf32(float f) {
    uint32_t r;
    asm("cvt.rna.tf32.f32 %0, %1;" : "=r"(r) : "f"(f));
    return __uint_as_float(r);
}
__device__ __forceinline__ uint32_t smem_u32(const void* p) {
    uint32_t a;
    asm("{ .reg .u64 t; cvta.to.shared.u64 t, %1; cvt.u32.u64 %0, t; }"
        : "=r"(a) : "l"(p));
    return a;
}
__device__ __forceinline__ void cp_async16(uint32_t dst, const void* src) {
    asm volatile("cp.async.cg.shared.global [%0], [%1], 16;"
                 :: "r"(dst), "l"(src) : "memory");
}
__device__ __forceinline__ void cp_commit() {
    asm volatile("cp.async.commit_group;" ::: "memory");
}
template <int N>
__device__ __forceinline__ void cp_wait() {
    asm volatile("cp.async.wait_group %0;" :: "n"(N) : "memory");
}
__device__ __forceinline__ void mma_tf32(float* c, const uint32_t* a, const uint32_t* b) {
    asm volatile(
        "mma.sync.aligned.m16n8k8.row.col.f32.tf32.tf32.f32 "
        "{%0,%1,%2,%3}, {%4,%5,%6,%7}, {%8,%9}, {%0,%1,%2,%3};"
        : "+f"(c[0]), "+f"(c[1]), "+f"(c[2]), "+f"(c[3])
        : "r"(a[0]), "r"(a[1]), "r"(a[2]), "r"(a[3]), "r"(b[0]), "r"(b[1]));
}

// ---------------- K1: init deg=2.0 (self-loop) and cnt=0 ---------------------
__global__ void init_kernel() {
    int n = blockIdx.x * blockDim.x + threadIdx.x;
    if (n < NN) { g_deg[n] = 2.0f; g_cnt[n] = 0; }
}

// ---------------- K2: accumulate edge weights + in-degree histogram ----------
__global__ void deg_acc_kernel(const int* __restrict__ ei, const float* __restrict__ w) {
    int e = blockIdx.x * blockDim.x + threadIdx.x;
    if (e < EE) {
        int c = ei[EE + e];
        atomicAdd(&g_deg[c], w[e]);
        atomicAdd(&g_cnt[c], 1);
    }
}

// ---------------- K3: dinv = rsqrt(deg) ---------------------------------------
__global__ void dinv_kernel() {
    int n = blockIdx.x * blockDim.x + threadIdx.x;
    if (n < NN) {
        float d = g_deg[n];
        g_dinv[n] = (d > 0.0f) ? rsqrtf(d) : 0.0f;
    }
}

// ---------------- K4: exclusive scan of g_cnt (single CTA, 1024 threads) -----
#define SCAN_CHUNK 20    // 1024 * 20 = 20480 >= NN
__global__ __launch_bounds__(1024)
void scan_kernel() {
    __shared__ int wsum[32];
    const int t    = threadIdx.x;
    const int lane = t & 31;
    const int wid  = t >> 5;
    const int base = t * SCAN_CHUNK;

    int loc[SCAN_CHUNK];
    int s = 0;
    #pragma unroll
    for (int i = 0; i < SCAN_CHUNK; i++) {
        int idx = base + i;
        int v = (idx < NN) ? g_cnt[idx] : 0;
        loc[i] = s;
        s += v;
    }
    // warp inclusive scan of thread totals
    int incl = s;
    #pragma unroll
    for (int off = 1; off < 32; off <<= 1) {
        int n = __shfl_up_sync(0xFFFFFFFFu, incl, off);
        if (lane >= off) incl += n;
    }
    int excl = incl - s;
    if (lane == 31) wsum[wid] = incl;
    __syncthreads();
    if (wid == 0) {
        int v = wsum[lane];
        int i2 = v;
        #pragma unroll
        for (int off = 1; off < 32; off <<= 1) {
            int n = __shfl_up_sync(0xFFFFFFFFu, i2, off);
            if (lane >= off) i2 += n;
        }
        wsum[lane] = i2 - v;   // exclusive warp base
    }
    __syncthreads();
    const int tbase = excl + wsum[wid];
    #pragma unroll
    for (int i = 0; i < SCAN_CHUNK; i++) {
        int idx = base + i;
        if (idx < NN) {
            int o = tbase + loc[i];
            g_off[idx]  = o;
            g_off2[idx] = o;
        }
    }
}

// ---------------- K5: CSR fill (src row + coef, sorted by dst) ---------------
__global__ void fill_kernel(const int* __restrict__ ei, const float* __restrict__ w) {
    int e = blockIdx.x * blockDim.x + threadIdx.x;
    if (e >= EE) return;
    int r = ei[e];
    int c = ei[EE + e];
    int i = atomicAdd(&g_off2[c], 1);
    g_srow[i]  = r;
    g_scoef[i] = g_dinv[r] * w[e] * g_dinv[c];
}

// ---------------- K6a: round x to tf32 into padded buffer --------------------
__global__ __launch_bounds__(256)
void cvt_x_kernel(const float* __restrict__ x) {
    int i = blockIdx.x * blockDim.x + threadIdx.x;   // float4 index within field
    int f = blockIdx.y;
    const int per_field4 = NN * DD / 4;
    if (i >= per_field4) return;
    float4 v = *(const float4*)(x + (size_t)f * NN * DD + (size_t)i * 4);
    v.x = f2tf32(v.x); v.y = f2tf32(v.y); v.z = f2tf32(v.z); v.w = f2tf32(v.w);
    *(float4*)(g_xa + (size_t)f * NP * DD + (size_t)i * 4) = v;
}

// ---------------- K6b: build combined B matrix (tf32) ------------------------
__global__ __launch_bounds__(256)
void build_bc_kernel(const float* __restrict__ Wg, const float* __restrict__ Wr,
                     const float* __restrict__ Wh) {
    int i = blockIdx.x * blockDim.x + threadIdx.x;   // over DD*NC
    int f = blockIdx.y;
    if (i >= DD * NC) return;
    int k = i / NC;
    int n = i - k * NC;
    float v;
    if (n < 256)       v = Wg[(size_t)f * DD * OO + (size_t)k * OO + n];
    else if (n < 512)  v = Wr[(size_t)f * OO * DD + (size_t)(n - 256) * DD + k];
    else               v = Wh[(size_t)f * DD * OO + (size_t)k * OO + (n - 512)];
    g_bc[(size_t)f * DD * NC + i] = f2tf32(v);
}

// ---------------- K7: HMMA tf32 fused GEMM ------------------------------------
#define BM 128
#define BN 128
#define BK 32
#define ASTRIDE 36
#define BSTRIDE 136
#define A_BYTES (BM * ASTRIDE * 4)
#define B_BYTES (BK * BSTRIDE * 4)
#define SMEM_GEMM (2 * (A_BYTES + B_BYTES))

__global__ __launch_bounds__(256, 2)
void gemm_kernel() {
    extern __shared__ float sm[];
    const uint32_t smb = smem_u32(sm);
    const uint32_t smA[2] = { smb, smb + A_BYTES };
    const uint32_t smB[2] = { smb + 2 * A_BYTES, smb + 2 * A_BYTES + B_BYTES };

    const int tid = threadIdx.x;
    const int wid = tid >> 5;
    const int lid = tid & 31;
    const int gid = lid >> 2;
    const int tig = lid & 3;
    const int wm  = wid & 3;
    const int wn  = wid >> 2;

    const int f     = blockIdx.z;
    const int mBase = blockIdx.x * BM;
    const int nBase = blockIdx.y * BN;

    const float* aSrc = g_xa + (size_t)f * NP * DD;
    const float* bSrc = g_bc + (size_t)f * DD * NC;

    const int ar = tid >> 1;
    const int aq = (tid & 1) * 4;
    const int br = tid >> 3;
    const int bq = (tid & 7) * 4;

    {
        const float* ap = aSrc + (size_t)(mBase + ar) * DD + aq;
        cp_async16(smA[0] + (uint32_t)(ar * ASTRIDE + aq) * 4, ap);
        cp_async16(smA[0] + (uint32_t)(ar * ASTRIDE + aq + 8) * 4, ap + 8);
        cp_async16(smA[0] + (uint32_t)(ar * ASTRIDE + aq + 16) * 4, ap + 16);
        cp_async16(smA[0] + (uint32_t)(ar * ASTRIDE + aq + 24) * 4, ap + 24);
        const float* bp = bSrc + (size_t)br * NC + nBase + bq;
        cp_async16(smB[0] + (uint32_t)(br * BSTRIDE + bq) * 4, bp);
        cp_async16(smB[0] + (uint32_t)(br * BSTRIDE + bq + 32) * 4, bp + 32);
        cp_async16(smB[0] + (uint32_t)(br * BSTRIDE + bq + 64) * 4, bp + 64);
        cp_async16(smB[0] + (uint32_t)(br * BSTRIDE + bq + 96) * 4, bp + 96);
        cp_commit();
    }

    float c[2][8][4];
    #pragma unroll
    for (int im = 0; im < 2; im++)
        #pragma unroll
        for (int in = 0; in < 8; in++)
            #pragma unroll
            for (int r = 0; r < 4; r++) c[im][in][r] = 0.0f;

    for (int kc = 0; kc < 8; kc++) {
        const int buf = kc & 1;

        if (kc < 7) {
            const int nb = buf ^ 1;
            const int kcol = (kc + 1) * BK;
            const float* ap = aSrc + (size_t)(mBase + ar) * DD + kcol + aq;
            cp_async16(smA[nb] + (uint32_t)(ar * ASTRIDE + aq) * 4, ap);
            cp_async16(smA[nb] + (uint32_t)(ar * ASTRIDE + aq + 8) * 4, ap + 8);
            cp_async16(smA[nb] + (uint32_t)(ar * ASTRIDE + aq + 16) * 4, ap + 16);
            cp_async16(smA[nb] + (uint32_t)(ar * ASTRIDE + aq + 24) * 4, ap + 24);
            const float* bp = bSrc + (size_t)(kcol + br) * NC + nBase + bq;
            cp_async16(smB[nb] + (uint32_t)(br * BSTRIDE + bq) * 4, bp);
            cp_async16(smB[nb] + (uint32_t)(br * BSTRIDE + bq + 32) * 4, bp + 32);
            cp_async16(smB[nb] + (uint32_t)(br * BSTRIDE + bq + 64) * 4, bp + 64);
            cp_async16(smB[nb] + (uint32_t)(br * BSTRIDE + bq + 96) * 4, bp + 96);
            cp_commit();
            cp_wait<1>();
        } else {
            cp_wait<0>();
        }
        __syncthreads();

        const float* As = sm + (buf ? BM * ASTRIDE : 0);
        const float* Bs = sm + 2 * BM * ASTRIDE + (buf ? BK * BSTRIDE : 0);

        #pragma unroll
        for (int ks = 0; ks < 4; ks++) {
            const int k0 = ks * 8;
            uint32_t a[2][4];
            #pragma unroll
            for (int im = 0; im < 2; im++) {
                const int m0 = wm * 32 + im * 16 + gid;
                a[im][0] = __float_as_uint(As[(m0)     * ASTRIDE + k0 + tig]);
                a[im][1] = __float_as_uint(As[(m0 + 8) * ASTRIDE + k0 + tig]);
                a[im][2] = __float_as_uint(As[(m0)     * ASTRIDE + k0 + tig + 4]);
                a[im][3] = __float_as_uint(As[(m0 + 8) * ASTRIDE + k0 + tig + 4]);
            }
            uint32_t b[8][2];
            #pragma unroll
            for (int in = 0; in < 8; in++) {
                const int n0 = wn * 64 + in * 8 + gid;
                b[in][0] = __float_as_uint(Bs[(k0 + tig)     * BSTRIDE + n0]);
                b[in][1] = __float_as_uint(Bs[(k0 + tig + 4) * BSTRIDE + n0]);
            }
            #pragma unroll
            for (int im = 0; im < 2; im++)
                #pragma unroll
                for (int in = 0; in < 8; in++)
                    mma_tf32(c[im][in], a[im], b[in]);
        }
        __syncthreads();
    }

    // ---- epilogue: write xg / res / gate ------------------------------------
    const int nb0 = nBase + wn * 64;
    const int gsel = nb0 >> 8;            // 0: xg, 1: res, 2: gate
    const int o0 = nb0 & 255;

    #pragma unroll
    for (int im = 0; im < 2; im++) {
        const int r0 = mBase + wm * 32 + im * 16 + gid;
        #pragma unroll
        for (int half = 0; half < 2; half++) {
            const int m = r0 + half * 8;
            if (m >= NN) continue;
            size_t rowbase = ((size_t)f * NN + m) * OO;
            if (gsel == 0) {
                #pragma unroll
                for (int in = 0; in < 8; in++) {
                    const int o = o0 + in * 8 + 2 * tig;
                    *(float2*)&g_xg[rowbase + o] =
                        make_float2(c[im][in][half * 2], c[im][in][half * 2 + 1]);
                }
            } else if (gsel == 1) {
                #pragma unroll
                for (int in = 0; in < 8; in++) {
                    const int o = o0 + in * 8 + 2 * tig;
                    *(float2*)&g_res[rowbase + o] =
                        make_float2(c[im][in][half * 2], c[im][in][half * 2 + 1]);
                }
            } else {
                #pragma unroll
                for (int in = 0; in < 8; in++) {
                    const int o = o0 + in * 8 + 2 * tig;
                    float2 v;
                    v.x = 1.0f / (1.0f + __expf(-c[im][in][half * 2]));
                    v.y = 1.0f / (1.0f + __expf(-c[im][in][half * 2 + 1]));
                    *(float2*)&g_gate[rowbase + o] = v;
                }
            }
        }
    }
}

// ---------------- K8: CSR gather + highway combine + leaky_relu --------------
// Thread = (dst node c, float4 slot j in O). 64 threads per dst share edge list
// (uniform loop, L1-broadcast metadata). Fuses self-loop seed, edge gather,
// highway gate and activation; writes final output.
__global__ __launch_bounds__(256)
void gather_combine_kernel(float* __restrict__ out) {
    int idx = blockIdx.x * blockDim.x + threadIdx.x;   // over NN * 64
    int f   = blockIdx.y;
    int c   = idx >> 6;
    int j   = idx & 63;
    if (c >= NN) return;

    const float* xgf = g_xg + (size_t)f * NN * OO;

    float di = g_dinv[c];
    float sl = 2.0f * di * di;

    float4 acc = *(const float4*)(xgf + (size_t)c * OO + j * 4);
    acc.x *= sl; acc.y *= sl; acc.z *= sl; acc.w *= sl;

    const int s0  = g_off[c];
    const int cnt = g_cnt[c];
    for (int k = 0; k < cnt; k++) {
        int   r  = g_srow[s0 + k];
        float cf = g_scoef[s0 + k];
        float4 v = *(const float4*)(xgf + (size_t)r * OO + j * 4);
        acc.x = fmaf(cf, v.x, acc.x);
        acc.y = fmaf(cf, v.y, acc.y);
        acc.z = fmaf(cf, v.z, acc.z);
        acc.w = fmaf(cf, v.w, acc.w);
    }

    size_t base = ((size_t)f * NN + c) * OO + j * 4;
    float4 g = *(const float4*)&g_gate[base];
    float4 r = *(const float4*)&g_res[base];

    float4 y;
    y.x = g.x * acc.x + (1.0f - g.x) * r.x;
    y.y = g.y * acc.y + (1.0f - g.y) * r.y;
    y.z = g.z * acc.z + (1.0f - g.z) * r.z;
    y.w = g.w * acc.w + (1.0f - g.w) * r.w;

    y.x = (y.x >= 0.0f) ? y.x : NEG_SLOPE * y.x;
    y.y = (y.y >= 0.0f) ? y.y : NEG_SLOPE * y.y;
    y.z = (y.z >= 0.0f) ? y.z : NEG_SLOPE * y.z;
    y.w = (y.w >= 0.0f) ? y.w : NEG_SLOPE * y.w;

    *(float4*)(out + base) = y;
}

// ---------------- launch ------------------------------------------------------
extern "C" void kernel_launch(void* const* d_in, const int* in_sizes, int n_in,
                              void* d_out, int out_size) {
    const float* x  = (const float*)d_in[0];
    const int*   ei = (const int*)  d_in[1];
    const float* w  = (const float*)d_in[2];
    const float* Wg = (const float*)d_in[3];
    const float* Wr = (const float*)d_in[4];
    const float* Wh = (const float*)d_in[5];
    float* out = (float*)d_out;

    init_kernel   <<<(NN + 255) / 256, 256>>>();
    deg_acc_kernel<<<(EE + 255) / 256, 256>>>(ei, w);
    dinv_kernel   <<<(NN + 255) / 256, 256>>>();
    scan_kernel   <<<1, 1024>>>();
    fill_kernel   <<<(EE + 255) / 256, 256>>>(ei, w);

    {
        int per_field4 = NN * DD / 4;
        dim3 grid((per_field4 + 255) / 256, FF);
        cvt_x_kernel<<<grid, 256>>>(x);
    }
    {
        dim3 grid((DD * NC + 255) / 256, FF);
        build_bc_kernel<<<grid, 256>>>(Wg, Wr, Wh);
    }

    cudaFuncSetAttribute(gemm_kernel,
                         cudaFuncAttributeMaxDynamicSharedMemorySize, SMEM_GEMM);
    dim3 ggrid(NP / BM, NC / BN, FF);    // (157, 6, 3)
    gemm_kernel<<<ggrid, 256, SMEM_GEMM>>>();

    dim3 cgrid((NN * 64 + 255) / 256, FF);   // (5000, 3)
    gather_combine_kernel<<<cgrid, 256>>>(out);
}

// round 5
// speedup vs baseline: 3.3877x; 1.0064x over previous
#include <cuda_runtime.h>
#include <math.h>
#include <stdint.h>

// Problem constants
#define FF 3
#define NN 20000
#define NP 20096          // NN padded to multiple of 128 (M-tile)
#define DD 256
#define OO 256
#define NC 768            // combined N: [xg | res | gate]
#define EE 320000
#define NEG_SLOPE 0.01f

// ---------------- scratch (__device__ globals; no allocation allowed) -------
__device__ float g_xa  [FF * NP * DD];   // x rounded to tf32, padded rows
__device__ float g_bc  [FF * DD * NC];   // combined B (tf32): Wg | Wr^T | Wh
__device__ float g_xg  [FF * NN * OO];   // x @ Wg
__device__ float g_res [FF * NN * OO];   // x @ Wr^T
__device__ float g_gate[FF * NN * OO];   // sigmoid(x @ Wh)
__device__ float g_deg [NN];
__device__ float g_dinv[NN];
__device__ int   g_cnt [NN];             // in-degree (edges only)
__device__ int   g_off [NN];             // CSR offsets (stable)
__device__ int   g_off2[NN];             // CSR fill cursors
__device__ long long g_edge[EE];         // packed (src_row, coef) sorted by dst

// ---------------- helpers -----------------------------------------------------
__device__ __forceinline__ float f2tf32(float f) {
    uint32_t r;
    asm("cvt.rna.tf32.f32 %0, %1;" : "=r"(r) : "f"(f));
    return __uint_as_float(r);
}
__device__ __forceinline__ uint32_t smem_u32(const void* p) {
    uint32_t a;
    asm("{ .reg .u64 t; cvta.to.shared.u64 t, %1; cvt.u32.u64 %0, t; }"
        : "=r"(a) : "l"(p));
    return a;
}
__device__ __forceinline__ void cp_async16(uint32_t dst, const void* src) {
    asm volatile("cp.async.cg.shared.global [%0], [%1], 16;"
                 :: "r"(dst), "l"(src) : "memory");
}
__device__ __forceinline__ void cp_commit() {
    asm volatile("cp.async.commit_group;" ::: "memory");
}
template <int N>
__device__ __forceinline__ void cp_wait() {
    asm volatile("cp.async.wait_group %0;" :: "n"(N) : "memory");
}
__device__ __forceinline__ void mma_tf32(float* c, const uint32_t* a, const uint32_t* b) {
    asm volatile(
        "mma.sync.aligned.m16n8k8.row.col.f32.tf32.tf32.f32 "
        "{%0,%1,%2,%3}, {%4,%5,%6,%7}, {%8,%9}, {%0,%1,%2,%3};"
        : "+f"(c[0]), "+f"(c[1]), "+f"(c[2]), "+f"(c[3])
        : "r"(a[0]), "r"(a[1]), "r"(a[2]), "r"(a[3]), "r"(b[0]), "r"(b[1]));
}

// ---------------- L1: init deg=2.0 (self-loop) and cnt=0 ---------------------
__global__ void init_kernel() {
    int n = blockIdx.x * blockDim.x + threadIdx.x;
    if (n < NN) { g_deg[n] = 2.0f; g_cnt[n] = 0; }
}

// ---------------- L2: merged cvt_x + build_bc --------------------------------
// blockIdx.x < 5000: tf32-round x into padded g_xa (float4 granularity)
// else:              build combined tf32 B matrix
__global__ __launch_bounds__(256)
void prep_kernel(const float* __restrict__ x, const float* __restrict__ Wg,
                 const float* __restrict__ Wr, const float* __restrict__ Wh) {
    const int f = blockIdx.y;
    if (blockIdx.x < 5000) {
        int i = blockIdx.x * 256 + threadIdx.x;      // float4 index within field
        float4 v = *(const float4*)(x + (size_t)f * NN * DD + (size_t)i * 4);
        v.x = f2tf32(v.x); v.y = f2tf32(v.y); v.z = f2tf32(v.z); v.w = f2tf32(v.w);
        *(float4*)(g_xa + (size_t)f * NP * DD + (size_t)i * 4) = v;
    } else {
        int i = (blockIdx.x - 5000) * 256 + threadIdx.x;  // over DD*NC = 196608
        int k = i / NC;
        int n = i - k * NC;
        float v;
        if (n < 256)       v = Wg[(size_t)f * DD * OO + (size_t)k * OO + n];
        else if (n < 512)  v = Wr[(size_t)f * OO * DD + (size_t)(n - 256) * DD + k];
        else               v = Wh[(size_t)f * DD * OO + (size_t)k * OO + (n - 512)];
        g_bc[(size_t)f * DD * NC + i] = f2tf32(v);
    }
}

// ---------------- L3: accumulate edge weights + in-degree histogram ----------
__global__ void deg_acc_kernel(const int* __restrict__ ei, const float* __restrict__ w) {
    int e = blockIdx.x * blockDim.x + threadIdx.x;
    if (e < EE) {
        int c = ei[EE + e];
        atomicAdd(&g_deg[c], w[e]);
        atomicAdd(&g_cnt[c], 1);
    }
}

// ---------------- L4: scan of g_cnt + dinv (single CTA, 1024 threads) --------
// NN = 20000 = 1000 threads * 20 ints (5 x int4 each, fully vectorized).
#define SCAN_CHUNK 20
__global__ __launch_bounds__(1024)
void scan_dinv_kernel() {
    __shared__ int wsum[32];
    const int t    = threadIdx.x;
    const int lane = t & 31;
    const int wid  = t >> 5;
    const int base = t * SCAN_CHUNK;
    const bool active = (base < NN);      // threads 0..999

    int v[SCAN_CHUNK];
    if (active) {
        #pragma unroll
        for (int q = 0; q < 5; q++) {
            int4 c4 = *(const int4*)(g_cnt + base + q * 4);
            v[q * 4 + 0] = c4.x; v[q * 4 + 1] = c4.y;
            v[q * 4 + 2] = c4.z; v[q * 4 + 3] = c4.w;
        }
    } else {
        #pragma unroll
        for (int i = 0; i < SCAN_CHUNK; i++) v[i] = 0;
    }

    int loc[SCAN_CHUNK];
    int s = 0;
    #pragma unroll
    for (int i = 0; i < SCAN_CHUNK; i++) { loc[i] = s; s += v[i]; }

    // warp inclusive scan of thread totals
    int incl = s;
    #pragma unroll
    for (int off = 1; off < 32; off <<= 1) {
        int n = __shfl_up_sync(0xFFFFFFFFu, incl, off);
        if (lane >= off) incl += n;
    }
    int excl = incl - s;
    if (lane == 31) wsum[wid] = incl;
    __syncthreads();
    if (wid == 0) {
        int vv = wsum[lane];
        int i2 = vv;
        #pragma unroll
        for (int off = 1; off < 32; off <<= 1) {
            int n = __shfl_up_sync(0xFFFFFFFFu, i2, off);
            if (lane >= off) i2 += n;
        }
        wsum[lane] = i2 - vv;   // exclusive warp base
    }
    __syncthreads();

    if (active) {
        const int tbase = excl + wsum[wid];
        int o4[SCAN_CHUNK];
        #pragma unroll
        for (int i = 0; i < SCAN_CHUNK; i++) o4[i] = tbase + loc[i];
        #pragma unroll
        for (int q = 0; q < 5; q++) {
            int4 ov = make_int4(o4[q*4], o4[q*4+1], o4[q*4+2], o4[q*4+3]);
            *(int4*)(g_off  + base + q * 4) = ov;
            *(int4*)(g_off2 + base + q * 4) = ov;
        }
    }

    // fold dinv here (deg complete after deg_acc launch)
    for (int n = t; n < NN; n += 1024) {
        float d = g_deg[n];
        g_dinv[n] = (d > 0.0f) ? rsqrtf(d) : 0.0f;
    }
}

// ---------------- L5: CSR fill (packed src+coef, sorted by dst) --------------
__global__ void fill_kernel(const int* __restrict__ ei, const float* __restrict__ w) {
    int e = blockIdx.x * blockDim.x + threadIdx.x;
    if (e >= EE) return;
    int r = ei[e];
    int c = ei[EE + e];
    float cf = g_dinv[r] * w[e] * g_dinv[c];
    int i = atomicAdd(&g_off2[c], 1);
    long long pk = ((long long)__float_as_int(cf) << 32) | (unsigned int)r;
    g_edge[i] = pk;
}

// ---------------- L6: HMMA tf32 fused GEMM ------------------------------------
#define BM 128
#define BN 128
#define BK 32
#define ASTRIDE 36
#define BSTRIDE 136
#define A_BYTES (BM * ASTRIDE * 4)
#define B_BYTES (BK * BSTRIDE * 4)
#define SMEM_GEMM (2 * (A_BYTES + B_BYTES))

__global__ __launch_bounds__(256, 2)
void gemm_kernel() {
    extern __shared__ float sm[];
    const uint32_t smb = smem_u32(sm);
    const uint32_t smA[2] = { smb, smb + A_BYTES };
    const uint32_t smB[2] = { smb + 2 * A_BYTES, smb + 2 * A_BYTES + B_BYTES };

    const int tid = threadIdx.x;
    const int wid = tid >> 5;
    const int lid = tid & 31;
    const int gid = lid >> 2;
    const int tig = lid & 3;
    const int wm  = wid & 3;
    const int wn  = wid >> 2;

    const int f     = blockIdx.z;
    const int mBase = blockIdx.x * BM;
    const int nBase = blockIdx.y * BN;

    const float* aSrc = g_xa + (size_t)f * NP * DD;
    const float* bSrc = g_bc + (size_t)f * DD * NC;

    const int ar = tid >> 1;
    const int aq = (tid & 1) * 4;
    const int br = tid >> 3;
    const int bq = (tid & 7) * 4;

    {
        const float* ap = aSrc + (size_t)(mBase + ar) * DD + aq;
        cp_async16(smA[0] + (uint32_t)(ar * ASTRIDE + aq) * 4, ap);
        cp_async16(smA[0] + (uint32_t)(ar * ASTRIDE + aq + 8) * 4, ap + 8);
        cp_async16(smA[0] + (uint32_t)(ar * ASTRIDE + aq + 16) * 4, ap + 16);
        cp_async16(smA[0] + (uint32_t)(ar * ASTRIDE + aq + 24) * 4, ap + 24);
        const float* bp = bSrc + (size_t)br * NC + nBase + bq;
        cp_async16(smB[0] + (uint32_t)(br * BSTRIDE + bq) * 4, bp);
        cp_async16(smB[0] + (uint32_t)(br * BSTRIDE + bq + 32) * 4, bp + 32);
        cp_async16(smB[0] + (uint32_t)(br * BSTRIDE + bq + 64) * 4, bp + 64);
        cp_async16(smB[0] + (uint32_t)(br * BSTRIDE + bq + 96) * 4, bp + 96);
        cp_commit();
    }

    float c[2][8][4];
    #pragma unroll
    for (int im = 0; im < 2; im++)
        #pragma unroll
        for (int in = 0; in < 8; in++)
            #pragma unroll
            for (int r = 0; r < 4; r++) c[im][in][r] = 0.0f;

    for (int kc = 0; kc < 8; kc++) {
        const int buf = kc & 1;

        if (kc < 7) {
            const int nb = buf ^ 1;
            const int kcol = (kc + 1) * BK;
            const float* ap = aSrc + (size_t)(mBase + ar) * DD + kcol + aq;
            cp_async16(smA[nb] + (uint32_t)(ar * ASTRIDE + aq) * 4, ap);
            cp_async16(smA[nb] + (uint32_t)(ar * ASTRIDE + aq + 8) * 4, ap + 8);
            cp_async16(smA[nb] + (uint32_t)(ar * ASTRIDE + aq + 16) * 4, ap + 16);
            cp_async16(smA[nb] + (uint32_t)(ar * ASTRIDE + aq + 24) * 4, ap + 24);
            const float* bp = bSrc + (size_t)(kcol + br) * NC + nBase + bq;
            cp_async16(smB[nb] + (uint32_t)(br * BSTRIDE + bq) * 4, bp);
            cp_async16(smB[nb] + (uint32_t)(br * BSTRIDE + bq + 32) * 4, bp + 32);
            cp_async16(smB[nb] + (uint32_t)(br * BSTRIDE + bq + 64) * 4, bp + 64);
            cp_async16(smB[nb] + (uint32_t)(br * BSTRIDE + bq + 96) * 4, bp + 96);
            cp_commit();
            cp_wait<1>();
        } else {
            cp_wait<0>();
        }
        __syncthreads();

        const float* As = sm + (buf ? BM * ASTRIDE : 0);
        const float* Bs = sm + 2 * BM * ASTRIDE + (buf ? BK * BSTRIDE : 0);

        #pragma unroll
        for (int ks = 0; ks < 4; ks++) {
            const int k0 = ks * 8;
            uint32_t a[2][4];
            #pragma unroll
            for (int im = 0; im < 2; im++) {
                const int m0 = wm * 32 + im * 16 + gid;
                a[im][0] = __float_as_uint(As[(m0)     * ASTRIDE + k0 + tig]);
                a[im][1] = __float_as_uint(As[(m0 + 8) * ASTRIDE + k0 + tig]);
                a[im][2] = __float_as_uint(As[(m0)     * ASTRIDE + k0 + tig + 4]);
                a[im][3] = __float_as_uint(As[(m0 + 8) * ASTRIDE + k0 + tig + 4]);
            }
            uint32_t b[8][2];
            #pragma unroll
            for (int in = 0; in < 8; in++) {
                const int n0 = wn * 64 + in * 8 + gid;
                b[in][0] = __float_as_uint(Bs[(k0 + tig)     * BSTRIDE + n0]);
                b[in][1] = __float_as_uint(Bs[(k0 + tig + 4) * BSTRIDE + n0]);
            }
            #pragma unroll
            for (int im = 0; im < 2; im++)
                #pragma unroll
                for (int in = 0; in < 8; in++)
                    mma_tf32(c[im][in], a[im], b[in]);
        }
        __syncthreads();
    }

    // ---- epilogue: write xg / res / gate ------------------------------------
    const int nb0 = nBase + wn * 64;
    const int gsel = nb0 >> 8;            // 0: xg, 1: res, 2: gate
    const int o0 = nb0 & 255;

    #pragma unroll
    for (int im = 0; im < 2; im++) {
        const int r0 = mBase + wm * 32 + im * 16 + gid;
        #pragma unroll
        for (int half = 0; half < 2; half++) {
            const int m = r0 + half * 8;
            if (m >= NN) continue;
            size_t rowbase = ((size_t)f * NN + m) * OO;
            if (gsel == 0) {
                #pragma unroll
                for (int in = 0; in < 8; in++) {
                    const int o = o0 + in * 8 + 2 * tig;
                    *(float2*)&g_xg[rowbase + o] =
                        make_float2(c[im][in][half * 2], c[im][in][half * 2 + 1]);
                }
            } else if (gsel == 1) {
                #pragma unroll
                for (int in = 0; in < 8; in++) {
                    const int o = o0 + in * 8 + 2 * tig;
                    *(float2*)&g_res[rowbase + o] =
                        make_float2(c[im][in][half * 2], c[im][in][half * 2 + 1]);
                }
            } else {
                #pragma unroll
                for (int in = 0; in < 8; in++) {
                    const int o = o0 + in * 8 + 2 * tig;
                    float2 v;
                    v.x = 1.0f / (1.0f + __expf(-c[im][in][half * 2]));
                    v.y = 1.0f / (1.0f + __expf(-c[im][in][half * 2 + 1]));
                    *(float2*)&g_gate[rowbase + o] = v;
                }
            }
        }
    }
}

// ---------------- L7: CSR gather + highway combine + leaky_relu --------------
__global__ __launch_bounds__(256)
void gather_combine_kernel(float* __restrict__ out) {
    int idx = blockIdx.x * blockDim.x + threadIdx.x;   // over NN * 64
    int f   = blockIdx.y;
    int c   = idx >> 6;
    int j   = idx & 63;
    if (c >= NN) return;

    const float* xgf = g_xg + (size_t)f * NN * OO;

    float di = g_dinv[c];
    float sl = 2.0f * di * di;

    float4 acc = *(const float4*)(xgf + (size_t)c * OO + j * 4);
    acc.x *= sl; acc.y *= sl; acc.z *= sl; acc.w *= sl;

    const int s0  = g_off[c];
    const int cnt = g_cnt[c];

    int k = 0;
    for (; k + 2 <= cnt; k += 2) {
        long long p0 = g_edge[s0 + k];
        long long p1 = g_edge[s0 + k + 1];
        int   r0 = (int)(unsigned int)(p0 & 0xFFFFFFFFll);
        int   r1 = (int)(unsigned int)(p1 & 0xFFFFFFFFll);
        float c0 = __int_as_float((int)(p0 >> 32));
        float c1 = __int_as_float((int)(p1 >> 32));
        float4 v0 = *(const float4*)(xgf + (size_t)r0 * OO + j * 4);
        float4 v1 = *(const float4*)(xgf + (size_t)r1 * OO + j * 4);
        acc.x = fmaf(c0, v0.x, acc.x); acc.x = fmaf(c1, v1.x, acc.x);
        acc.y = fmaf(c0, v0.y, acc.y); acc.y = fmaf(c1, v1.y, acc.y);
        acc.z = fmaf(c0, v0.z, acc.z); acc.z = fmaf(c1, v1.z, acc.z);
        acc.w = fmaf(c0, v0.w, acc.w); acc.w = fmaf(c1, v1.w, acc.w);
    }
    if (k < cnt) {
        long long p0 = g_edge[s0 + k];
        int   r0 = (int)(unsigned int)(p0 & 0xFFFFFFFFll);
        float c0 = __int_as_float((int)(p0 >> 32));
        float4 v0 = *(const float4*)(xgf + (size_t)r0 * OO + j * 4);
        acc.x = fmaf(c0, v0.x, acc.x);
        acc.y = fmaf(c0, v0.y, acc.y);
        acc.z = fmaf(c0, v0.z, acc.z);
        acc.w = fmaf(c0, v0.w, acc.w);
    }

    size_t base = ((size_t)f * NN + c) * OO + j * 4;
    float4 g = *(const float4*)&g_gate[base];
    float4 r = *(const float4*)&g_res[base];

    float4 y;
    y.x = g.x * acc.x + (1.0f - g.x) * r.x;
    y.y = g.y * acc.y + (1.0f - g.y) * r.y;
    y.z = g.z * acc.z + (1.0f - g.z) * r.z;
    y.w = g.w * acc.w + (1.0f - g.w) * r.w;

    y.x = (y.x >= 0.0f) ? y.x : NEG_SLOPE * y.x;
    y.y = (y.y >= 0.0f) ? y.y : NEG_SLOPE * y.y;
    y.z = (y.z >= 0.0f) ? y.z : NEG_SLOPE * y.z;
    y.w = (y.w >= 0.0f) ? y.w : NEG_SLOPE * y.w;

    *(float4*)(out + base) = y;
}

// ---------------- launch ------------------------------------------------------
extern "C" void kernel_launch(void* const* d_in, const int* in_sizes, int n_in,
                              void* d_out, int out_size) {
    const float* x  = (const float*)d_in[0];
    const int*   ei = (const int*)  d_in[1];
    const float* w  = (const float*)d_in[2];
    const float* Wg = (const float*)d_in[3];
    const float* Wr = (const float*)d_in[4];
    const float* Wh = (const float*)d_in[5];
    float* out = (float*)d_out;

    // launch order chosen so gemm_kernel is launch #6 (ncu -s 5 -c 1 target)
    init_kernel    <<<(NN + 255) / 256, 256>>>();                    // 1
    prep_kernel    <<<dim3(5768, FF), 256>>>(x, Wg, Wr, Wh);         // 2
    deg_acc_kernel <<<(EE + 255) / 256, 256>>>(ei, w);               // 3
    scan_dinv_kernel<<<1, 1024>>>();                                 // 4
    fill_kernel    <<<(EE + 255) / 256, 256>>>(ei, w);               // 5

    cudaFuncSetAttribute(gemm_kernel,
                         cudaFuncAttributeMaxDynamicSharedMemorySize, SMEM_GEMM);
    dim3 ggrid(NP / BM, NC / BN, FF);    // (157, 6, 3)
    gemm_kernel<<<ggrid, 256, SMEM_GEMM>>>();                        // 6

    dim3 cgrid((NN * 64 + 255) / 256, FF);   // (5000, 3)
    gather_combine_kernel<<<cgrid, 256>>>(out);                      // 7
}

// round 6
// speedup vs baseline: 3.4499x; 1.0184x over previous
#include <cuda_runtime.h>
#include <math.h>
#include <stdint.h>

// Problem constants
#define FF 3
#define NN 20000
#define DD 256
#define OO 256
#define NC 768            // combined N: [xg | res | gate]
#define EE 320000
#define NEG_SLOPE 0.01f

// ---------------- scratch (__device__ globals; no allocation allowed) -------
__device__ float g_bc  [FF * DD * NC];   // combined B (tf32): Wg | Wr^T | Wh
__device__ float g_xg  [FF * NN * OO];   // x @ Wg
__device__ float g_res [FF * NN * OO];   // x @ Wr^T
__device__ float g_gate[FF * NN * OO];   // sigmoid(x @ Wh)
__device__ float g_deg [NN];
__device__ int   g_cnt [NN];             // in-degree (edges only)
__device__ int   g_off [NN];             // CSR offsets (stable)
__device__ int   g_off2[NN];             // CSR fill cursors
__device__ long long g_edge[EE];         // packed (src_row, coef) sorted by dst

// ---------------- helpers -----------------------------------------------------
__device__ __forceinline__ float f2tf32(float f) {
    uint32_t r;
    asm("cvt.rna.tf32.f32 %0, %1;" : "=r"(r) : "f"(f));
    return __uint_as_float(r);
}
__device__ __forceinline__ uint32_t smem_u32(const void* p) {
    uint32_t a;
    asm("{ .reg .u64 t; cvta.to.shared.u64 t, %1; cvt.u32.u64 %0, t; }"
        : "=r"(a) : "l"(p));
    return a;
}
__device__ __forceinline__ void cp_async16(uint32_t dst, const void* src) {
    asm volatile("cp.async.cg.shared.global [%0], [%1], 16;"
                 :: "r"(dst), "l"(src) : "memory");
}
__device__ __forceinline__ void cp_commit() {
    asm volatile("cp.async.commit_group;" ::: "memory");
}
template <int N>
__device__ __forceinline__ void cp_wait() {
    asm volatile("cp.async.wait_group %0;" :: "n"(N) : "memory");
}
__device__ __forceinline__ void mma_tf32(float* c, const uint32_t* a, const uint32_t* b) {
    asm volatile(
        "mma.sync.aligned.m16n8k8.row.col.f32.tf32.tf32.f32 "
        "{%0,%1,%2,%3}, {%4,%5,%6,%7}, {%8,%9}, {%0,%1,%2,%3};"
        : "+f"(c[0]), "+f"(c[1]), "+f"(c[2]), "+f"(c[3])
        : "r"(a[0]), "r"(a[1]), "r"(a[2]), "r"(a[3]), "r"(b[0]), "r"(b[1]));
}

// ---------------- L1: init deg=2.0 (self-loop) and cnt=0 ---------------------
__global__ void init_kernel() {
    int n = blockIdx.x * blockDim.x + threadIdx.x;
    if (n < NN) { g_deg[n] = 2.0f; g_cnt[n] = 0; }
}

// ---------------- L2: build combined B matrix (tf32) -------------------------
__global__ __launch_bounds__(256)
void prep_kernel(const float* __restrict__ Wg, const float* __restrict__ Wr,
                 const float* __restrict__ Wh) {
    const int f = blockIdx.y;
    int i = blockIdx.x * 256 + threadIdx.x;          // over DD*NC = 196608
    int k = i / NC;
    int n = i - k * NC;
    float v;
    if (n < 256)       v = Wg[(size_t)f * DD * OO + (size_t)k * OO + n];
    else if (n < 512)  v = Wr[(size_t)f * OO * DD + (size_t)(n - 256) * DD + k];
    else               v = Wh[(size_t)f * DD * OO + (size_t)k * OO + (n - 512)];
    g_bc[(size_t)f * DD * NC + i] = f2tf32(v);
}

// ---------------- L3: accumulate edge weights + in-degree histogram ----------
__global__ void deg_acc_kernel(const int* __restrict__ ei, const float* __restrict__ w) {
    int e = blockIdx.x * blockDim.x + threadIdx.x;
    if (e < EE) {
        int c = ei[EE + e];
        atomicAdd(&g_deg[c], w[e]);
        atomicAdd(&g_cnt[c], 1);
    }
}

// ---------------- L4 (launch #4): HMMA tf32 fused GEMM ------------------------
// C[f] = tf32(x[f]) (NNx256) @ Bc[f] (256x768), CTA tile 128x128x32.
// A path: direct LDG from x + inline cvt.rna.tf32 + STS (2-deep pipeline).
// B path: cp.async double buffer.
#define BM 128
#define BN 128
#define BK 32
#define ASTRIDE 36
#define BSTRIDE 136
#define A_BYTES (BM * ASTRIDE * 4)
#define B_BYTES (BK * BSTRIDE * 4)
#define SMEM_GEMM (2 * (A_BYTES + B_BYTES))

__global__ __launch_bounds__(256, 2)
void gemm_kernel(const float* __restrict__ x) {
    extern __shared__ float sm[];
    const uint32_t smb = smem_u32(sm);
    const uint32_t smB[2] = { smb + 2 * A_BYTES, smb + 2 * A_BYTES + B_BYTES };

    const int tid = threadIdx.x;
    const int wid = tid >> 5;
    const int lid = tid & 31;
    const int gid = lid >> 2;
    const int tig = lid & 3;
    const int wm  = wid & 3;
    const int wn  = wid >> 2;

    const int f     = blockIdx.z;
    const int mBase = blockIdx.x * BM;
    const int nBase = blockIdx.y * BN;

    const float* xf   = x    + (size_t)f * NN * DD;
    const float* bSrc = g_bc + (size_t)f * DD * NC;

    const int ar = tid >> 1;                 // A row 0..127
    const int aq = (tid & 1) * 4;            // A col base {0,4}
    const int br = tid >> 3;                 // B k-row 0..31
    const int bq = (tid & 7) * 4;            // B col group

    const int gm   = mBase + ar;
    const bool mok = (gm < NN);
    const float* arow = xf + (size_t)gm * DD;

    float4 va[4];
    // prologue: A(0) -> regs -> smem buf0; B(0) cp.async; A(1) -> regs
    #pragma unroll
    for (int q = 0; q < 4; q++)
        va[q] = mok ? *(const float4*)(arow + aq + 8 * q)
                    : make_float4(0.f, 0.f, 0.f, 0.f);
    {
        float* As0 = sm;   // buf0
        #pragma unroll
        for (int q = 0; q < 4; q++) {
            float* d = As0 + ar * ASTRIDE + aq + 8 * q;
            d[0] = f2tf32(va[q].x); d[1] = f2tf32(va[q].y);
            d[2] = f2tf32(va[q].z); d[3] = f2tf32(va[q].w);
        }
        const float* bp = bSrc + (size_t)br * NC + nBase + bq;
        cp_async16(smB[0] + (uint32_t)(br * BSTRIDE + bq) * 4, bp);
        cp_async16(smB[0] + (uint32_t)(br * BSTRIDE + bq + 32) * 4, bp + 32);
        cp_async16(smB[0] + (uint32_t)(br * BSTRIDE + bq + 64) * 4, bp + 64);
        cp_async16(smB[0] + (uint32_t)(br * BSTRIDE + bq + 96) * 4, bp + 96);
        cp_commit();
        #pragma unroll
        for (int q = 0; q < 4; q++)
            va[q] = mok ? *(const float4*)(arow + BK + aq + 8 * q)
                        : make_float4(0.f, 0.f, 0.f, 0.f);
    }

    float c[2][8][4];
    #pragma unroll
    for (int im = 0; im < 2; im++)
        #pragma unroll
        for (int in = 0; in < 8; in++)
            #pragma unroll
            for (int r = 0; r < 4; r++) c[im][in][r] = 0.0f;

    for (int kc = 0; kc < 8; kc++) {
        const int buf = kc & 1;

        cp_wait<0>();
        __syncthreads();   // B(kc) ready; A(kc) STS visible; buf^1 free (MMA(kc-1) done)

        if (kc < 7) {
            const int nb = buf ^ 1;
            // stage A(kc+1) from regs
            float* Asn = sm + (nb ? BM * ASTRIDE : 0);
            #pragma unroll
            for (int q = 0; q < 4; q++) {
                float* d = Asn + ar * ASTRIDE + aq + 8 * q;
                d[0] = f2tf32(va[q].x); d[1] = f2tf32(va[q].y);
                d[2] = f2tf32(va[q].z); d[3] = f2tf32(va[q].w);
            }
            // B(kc+1) cp.async
            const int kcol = (kc + 1) * BK;
            const float* bp = bSrc + (size_t)(kcol + br) * NC + nBase + bq;
            cp_async16(smB[nb] + (uint32_t)(br * BSTRIDE + bq) * 4, bp);
            cp_async16(smB[nb] + (uint32_t)(br * BSTRIDE + bq + 32) * 4, bp + 32);
            cp_async16(smB[nb] + (uint32_t)(br * BSTRIDE + bq + 64) * 4, bp + 64);
            cp_async16(smB[nb] + (uint32_t)(br * BSTRIDE + bq + 96) * 4, bp + 96);
            cp_commit();
            // prefetch A(kc+2)
            if (kc < 6) {
                const int kcol2 = (kc + 2) * BK;
                #pragma unroll
                for (int q = 0; q < 4; q++)
                    va[q] = mok ? *(const float4*)(arow + kcol2 + aq + 8 * q)
                                : make_float4(0.f, 0.f, 0.f, 0.f);
            }
        }

        const float* As = sm + (buf ? BM * ASTRIDE : 0);
        const float* Bs = sm + 2 * BM * ASTRIDE + (buf ? BK * BSTRIDE : 0);

        #pragma unroll
        for (int ks = 0; ks < 4; ks++) {
            const int k0 = ks * 8;
            uint32_t a[2][4];
            #pragma unroll
            for (int im = 0; im < 2; im++) {
                const int m0 = wm * 32 + im * 16 + gid;
                a[im][0] = __float_as_uint(As[(m0)     * ASTRIDE + k0 + tig]);
                a[im][1] = __float_as_uint(As[(m0 + 8) * ASTRIDE + k0 + tig]);
                a[im][2] = __float_as_uint(As[(m0)     * ASTRIDE + k0 + tig + 4]);
                a[im][3] = __float_as_uint(As[(m0 + 8) * ASTRIDE + k0 + tig + 4]);
            }
            uint32_t b[8][2];
            #pragma unroll
            for (int in = 0; in < 8; in++) {
                const int n0 = wn * 64 + in * 8 + gid;
                b[in][0] = __float_as_uint(Bs[(k0 + tig)     * BSTRIDE + n0]);
                b[in][1] = __float_as_uint(Bs[(k0 + tig + 4) * BSTRIDE + n0]);
            }
            #pragma unroll
            for (int im = 0; im < 2; im++)
                #pragma unroll
                for (int in = 0; in < 8; in++)
                    mma_tf32(c[im][in], a[im], b[in]);
        }
        __syncthreads();
    }

    // ---- epilogue: write xg / res / gate ------------------------------------
    const int nb0 = nBase + wn * 64;
    const int gsel = nb0 >> 8;            // 0: xg, 1: res, 2: gate
    const int o0 = nb0 & 255;

    #pragma unroll
    for (int im = 0; im < 2; im++) {
        const int r0 = mBase + wm * 32 + im * 16 + gid;
        #pragma unroll
        for (int half = 0; half < 2; half++) {
            const int m = r0 + half * 8;
            if (m >= NN) continue;
            size_t rowbase = ((size_t)f * NN + m) * OO;
            if (gsel == 0) {
                #pragma unroll
                for (int in = 0; in < 8; in++) {
                    const int o = o0 + in * 8 + 2 * tig;
                    *(float2*)&g_xg[rowbase + o] =
                        make_float2(c[im][in][half * 2], c[im][in][half * 2 + 1]);
                }
            } else if (gsel == 1) {
                #pragma unroll
                for (int in = 0; in < 8; in++) {
                    const int o = o0 + in * 8 + 2 * tig;
                    *(float2*)&g_res[rowbase + o] =
                        make_float2(c[im][in][half * 2], c[im][in][half * 2 + 1]);
                }
            } else {
                #pragma unroll
                for (int in = 0; in < 8; in++) {
                    const int o = o0 + in * 8 + 2 * tig;
                    float2 v;
                    v.x = 1.0f / (1.0f + __expf(-c[im][in][half * 2]));
                    v.y = 1.0f / (1.0f + __expf(-c[im][in][half * 2 + 1]));
                    *(float2*)&g_gate[rowbase + o] = v;
                }
            }
        }
    }
}

// ---------------- L5: scan of g_cnt (single CTA, 1024 threads) ---------------
#define SCAN_CHUNK 20
__global__ __launch_bounds__(1024)
void scan_kernel() {
    __shared__ int wsum[32];
    const int t    = threadIdx.x;
    const int lane = t & 31;
    const int wid  = t >> 5;
    const int base = t * SCAN_CHUNK;
    const bool active = (base < NN);      // threads 0..999

    int v[SCAN_CHUNK];
    if (active) {
        #pragma unroll
        for (int q = 0; q < 5; q++) {
            int4 c4 = *(const int4*)(g_cnt + base + q * 4);
            v[q * 4 + 0] = c4.x; v[q * 4 + 1] = c4.y;
            v[q * 4 + 2] = c4.z; v[q * 4 + 3] = c4.w;
        }
    } else {
        #pragma unroll
        for (int i = 0; i < SCAN_CHUNK; i++) v[i] = 0;
    }

    int loc[SCAN_CHUNK];
    int s = 0;
    #pragma unroll
    for (int i = 0; i < SCAN_CHUNK; i++) { loc[i] = s; s += v[i]; }

    int incl = s;
    #pragma unroll
    for (int off = 1; off < 32; off <<= 1) {
        int n = __shfl_up_sync(0xFFFFFFFFu, incl, off);
        if (lane >= off) incl += n;
    }
    int excl = incl - s;
    if (lane == 31) wsum[wid] = incl;
    __syncthreads();
    if (wid == 0) {
        int vv = wsum[lane];
        int i2 = vv;
        #pragma unroll
        for (int off = 1; off < 32; off <<= 1) {
            int n = __shfl_up_sync(0xFFFFFFFFu, i2, off);
            if (lane >= off) i2 += n;
        }
        wsum[lane] = i2 - vv;
    }
    __syncthreads();

    if (active) {
        const int tbase = excl + wsum[wid];
        int o4[SCAN_CHUNK];
        #pragma unroll
        for (int i = 0; i < SCAN_CHUNK; i++) o4[i] = tbase + loc[i];
        #pragma unroll
        for (int q = 0; q < 5; q++) {
            int4 ov = make_int4(o4[q*4], o4[q*4+1], o4[q*4+2], o4[q*4+3]);
            *(int4*)(g_off  + base + q * 4) = ov;
            *(int4*)(g_off2 + base + q * 4) = ov;
        }
    }
}

// ---------------- L6: CSR fill (packed src+coef, sorted by dst) --------------
__global__ void fill_kernel(const int* __restrict__ ei, const float* __restrict__ w) {
    int e = blockIdx.x * blockDim.x + threadIdx.x;
    if (e >= EE) return;
    int r = ei[e];
    int c = ei[EE + e];
    float cf = rsqrtf(g_deg[r]) * w[e] * rsqrtf(g_deg[c]);
    int i = atomicAdd(&g_off2[c], 1);
    long long pk = ((long long)__float_as_int(cf) << 32) | (unsigned int)r;
    g_edge[i] = pk;
}

// ---------------- L7: CSR gather + highway combine + leaky_relu --------------
__global__ __launch_bounds__(256)
void gather_combine_kernel(float* __restrict__ out) {
    int idx = blockIdx.x * blockDim.x + threadIdx.x;   // over NN * 64
    int f   = blockIdx.y;
    int c   = idx >> 6;
    int j   = idx & 63;
    if (c >= NN) return;

    const float* xgf = g_xg + (size_t)f * NN * OO;

    float di = rsqrtf(g_deg[c]);
    float sl = 2.0f * di * di;

    float4 acc = *(const float4*)(xgf + (size_t)c * OO + j * 4);
    acc.x *= sl; acc.y *= sl; acc.z *= sl; acc.w *= sl;

    const int s0  = g_off[c];
    const int cnt = g_cnt[c];

    int k = 0;
    for (; k + 2 <= cnt; k += 2) {
        long long p0 = g_edge[s0 + k];
        long long p1 = g_edge[s0 + k + 1];
        int   r0 = (int)(unsigned int)(p0 & 0xFFFFFFFFll);
        int   r1 = (int)(unsigned int)(p1 & 0xFFFFFFFFll);
        float c0 = __int_as_float((int)(p0 >> 32));
        float c1 = __int_as_float((int)(p1 >> 32));
        float4 v0 = *(const float4*)(xgf + (size_t)r0 * OO + j * 4);
        float4 v1 = *(const float4*)(xgf + (size_t)r1 * OO + j * 4);
        acc.x = fmaf(c0, v0.x, acc.x); acc.x = fmaf(c1, v1.x, acc.x);
        acc.y = fmaf(c0, v0.y, acc.y); acc.y = fmaf(c1, v1.y, acc.y);
        acc.z = fmaf(c0, v0.z, acc.z); acc.z = fmaf(c1, v1.z, acc.z);
        acc.w = fmaf(c0, v0.w, acc.w); acc.w = fmaf(c1, v1.w, acc.w);
    }
    if (k < cnt) {
        long long p0 = g_edge[s0 + k];
        int   r0 = (int)(unsigned int)(p0 & 0xFFFFFFFFll);
        float c0 = __int_as_float((int)(p0 >> 32));
        float4 v0 = *(const float4*)(xgf + (size_t)r0 * OO + j * 4);
        acc.x = fmaf(c0, v0.x, acc.x);
        acc.y = fmaf(c0, v0.y, acc.y);
        acc.z = fmaf(c0, v0.z, acc.z);
        acc.w = fmaf(c0, v0.w, acc.w);
    }

    size_t base = ((size_t)f * NN + c) * OO + j * 4;
    float4 g = *(const float4*)&g_gate[base];
    float4 r = *(const float4*)&g_res[base];

    float4 y;
    y.x = g.x * acc.x + (1.0f - g.x) * r.x;
    y.y = g.y * acc.y + (1.0f - g.y) * r.y;
    y.z = g.z * acc.z + (1.0f - g.z) * r.z;
    y.w = g.w * acc.w + (1.0f - g.w) * r.w;

    y.x = (y.x >= 0.0f) ? y.x : NEG_SLOPE * y.x;
    y.y = (y.y >= 0.0f) ? y.y : NEG_SLOPE * y.y;
    y.z = (y.z >= 0.0f) ? y.z : NEG_SLOPE * y.z;
    y.w = (y.w >= 0.0f) ? y.w : NEG_SLOPE * y.w;

    *(float4*)(out + base) = y;
}

// ---------------- launch ------------------------------------------------------
extern "C" void kernel_launch(void* const* d_in, const int* in_sizes, int n_in,
                              void* d_out, int out_size) {
    const float* x  = (const float*)d_in[0];
    const int*   ei = (const int*)  d_in[1];
    const float* w  = (const float*)d_in[2];
    const float* Wg = (const float*)d_in[3];
    const float* Wr = (const float*)d_in[4];
    const float* Wh = (const float*)d_in[5];
    float* out = (float*)d_out;

    // gemm is launch #4 — observed ncu capture slot (-s 5 -c 1)
    init_kernel    <<<(NN + 255) / 256, 256>>>();                    // 1
    prep_kernel    <<<dim3(DD * NC / 256, FF), 256>>>(Wg, Wr, Wh);   // 2
    deg_acc_kernel <<<(EE + 255) / 256, 256>>>(ei, w);               // 3

    cudaFuncSetAttribute(gemm_kernel,
                         cudaFuncAttributeMaxDynamicSharedMemorySize, SMEM_GEMM);
    dim3 ggrid((NN + BM - 1) / BM, NC / BN, FF);    // (157, 6, 3)
    gemm_kernel<<<ggrid, 256, SMEM_GEMM>>>(x);                       // 4

    scan_kernel    <<<1, 1024>>>();                                  // 5
    fill_kernel    <<<(EE + 255) / 256, 256>>>(ei, w);               // 6

    dim3 cgrid((NN * 64 + 255) / 256, FF);   // (5000, 3)
    gather_combine_kernel<<<cgrid, 256>>>(out);                      // 7
}